// round 15
// baseline (speedup 1.0000x reference)
#include <cuda_runtime.h>

// PyramidROIAlign: 2 ROIs per 128-thread block (grid B*N/2 = single wave on
// 148 SMs), R8-proven inner body: per iteration 2 points x 2 halves =
// 16 burst LDG.128, streaming (.cs) stores. Prologue builds both ROIs'
// per-point tables (98 threads) -> no mid-kernel sync.
// Output [B,N,7,7,256] f32.

#define POOLN   49
#define NPTS    98            // 2 ROIs worth of pool points
#define C4V     64
#define PER_ROI (POOLN * C4V)

#define LD4(v, addr)                                                           \
    asm volatile("ld.global.nc.v4.f32 {%0,%1,%2,%3}, [%4];"                    \
        : "=f"((v).x), "=f"((v).y), "=f"((v).z), "=f"((v).w) : "l"(addr))

__device__ __forceinline__ float4 bilin4(float4 wt, float4 a, float4 b,
                                         float4 c, float4 d)
{
    float4 o;
    o.x = wt.x * a.x + wt.y * b.x + wt.z * c.x + wt.w * d.x;
    o.y = wt.x * a.y + wt.y * b.y + wt.z * c.y + wt.w * d.y;
    o.z = wt.x * a.z + wt.y * b.z + wt.z * c.z + wt.w * d.z;
    o.w = wt.x * a.w + wt.y * b.w + wt.z * c.w + wt.w * d.w;
    return o;
}

__device__ __forceinline__ void st4cs(float4* addr, float4 v)
{
    asm volatile("st.global.cs.v4.f32 [%0], {%1,%2,%3,%4};"
        :: "l"(addr), "f"(v.x), "f"(v.y), "f"(v.z), "f"(v.w));
}

__global__ void __launch_bounds__(128, 4) roi_align_kernel(
    const float* __restrict__ boxes,       // [B,N,4]
    const int*   __restrict__ image_shape, // [2]
    const float* __restrict__ p2,
    const float* __restrict__ p3,
    const float* __restrict__ p4,
    const float* __restrict__ p5,
    float*       __restrict__ out,         // [B,N,7,7,256]
    int N, int nroi)
{
    __shared__ int4          s_off[NPTS];  // corner offsets (float4 units)
    __shared__ float4        s_w[NPTS];    // expanded bilinear weights
    __shared__ const float4* s_fm[2];      // per-ROI feature map base

    const int roi0 = blockIdx.x * 2;       // this block: roi0, roi0+1
    const int tid  = threadIdx.x;
    const bool hasR1 = (roi0 + 1) < nroi;

    if (tid < NPTS) {
        int r    = (tid >= POOLN);         // 0 or 1
        int pidx = tid - r * POOLN;        // point within ROI
        int roi  = roi0 + r;
        int roiS = (r && !hasR1) ? roi0 : roi;  // safe clamp (dup data, no store)
        int b    = roiS / N;

        const float* bx = boxes + roiS * 4;
        float y1 = __ldg(bx + 0), x1 = __ldg(bx + 1);
        float y2 = __ldg(bx + 2), x2 = __ldg(bx + 3);
        float bh = y2 - y1, bw = x2 - x1;

        float img_area = (float)image_shape[0] * (float)image_shape[1];
        float scaled = sqrtf(bh * bw) * sqrtf(img_area) * (1.0f / 224.0f);
        float fl = rintf(log2f(scaled));
        fl = fminf(fmaxf(fl, -2.0f), 1.0f);     // lvl = 4+fl in [2,5]
        int lvl = 4 + (int)fl;
        int H = 256 >> (lvl - 2);
        int W = H;

        int py = pidx / 7;
        int px = pidx - py * 7;
        float ty = (float)py * (1.0f / 6.0f);
        float tx = (float)px * (1.0f / 6.0f);
        float ys = (y1 + bh * ty) * (float)(H - 1);
        float xs = (x1 + bw * tx) * (float)(W - 1);

        float y0f = floorf(ys);
        float x0f = floorf(xs);
        float wy = ys - y0f;
        float wx = xs - x0f;

        int y0  = min(H - 1, max(0, (int)y0f));
        int x0  = min(W - 1, max(0, (int)x0f));
        int y1i = min(H - 1, y0 + 1);
        int x1i = min(W - 1, x0 + 1);

        int base = b * H * W * C4V;             // float4 units, fits int32
        int r0o = base + y0  * W * C4V;
        int r1o = base + y1i * W * C4V;
        s_off[tid] = make_int4(r0o + x0  * C4V,
                               r0o + x1i * C4V,
                               r1o + x0  * C4V,
                               r1o + x1i * C4V);

        float iwy = 1.0f - wy, iwx = 1.0f - wx;
        s_w[tid] = make_float4(iwy * iwx, iwy * wx, wy * iwx, wy * wx);

        if (pidx == 0) {
            s_fm[r] = (lvl == 2) ? (const float4*)p2 :
                      (lvl == 3) ? (const float4*)p3 :
                      (lvl == 4) ? (const float4*)p4 : (const float4*)p5;
        }
    }
    __syncthreads();

    const int lane = tid & 31;
    const int wid  = tid >> 5;             // 0..3
    float4* __restrict__ out0 = (float4*)out + (long long)roi0 * PER_ROI;

    // Flat 98-point walk: warp wid takes pairs (ptA, ptA+2), ptA = wid, wid+4, ...
    for (int ptA = wid; ptA < NPTS; ptA += 4) {
        int  ptB  = ptA + 2;
        bool hasB = (ptB < NPTS);
        int  ptBs = hasB ? ptB : ptA;

        int rA = (ptA >= POOLN);
        int rB = (ptBs >= POOLN);

        const float4* fmA = s_fm[rA];
        const float4* fmB = s_fm[rB];

        int4   offA = s_off[ptA],  offB = s_off[ptBs];
        float4 wA   = s_w[ptA],    wB   = s_w[ptBs];

        const float4* pa0 = fmA + offA.x + lane;
        const float4* pa1 = fmA + offA.y + lane;
        const float4* pa2 = fmA + offA.z + lane;
        const float4* pa3 = fmA + offA.w + lane;
        const float4* pb0 = fmB + offB.x + lane;
        const float4* pb1 = fmB + offB.y + lane;
        const float4* pb2 = fmB + offB.z + lane;
        const float4* pb3 = fmB + offB.w + lane;

        float4 a00l, a01l, a10l, a11l, a00h, a01h, a10h, a11h;
        float4 b00l, b01l, b10l, b11l, b00h, b01h, b10h, b11h;

        // 16 back-to-back independent LDG.128
        LD4(a00l, pa0);      LD4(a01l, pa1);
        LD4(a10l, pa2);      LD4(a11l, pa3);
        LD4(a00h, pa0 + 32); LD4(a01h, pa1 + 32);
        LD4(a10h, pa2 + 32); LD4(a11h, pa3 + 32);
        LD4(b00l, pb0);      LD4(b01l, pb1);
        LD4(b10l, pb2);      LD4(b11l, pb3);
        LD4(b00h, pb0 + 32); LD4(b01h, pb1 + 32);
        LD4(b10h, pb2 + 32); LD4(b11h, pb3 + 32);

        bool stA = (rA == 0) || hasR1;
        if (stA) {
            float4 oAl = bilin4(wA, a00l, a01l, a10l, a11l);
            float4 oAh = bilin4(wA, a00h, a01h, a10h, a11h);
            float4* oA = out0 + ptA * C4V + lane;   // ptA*C4V spans both ROIs
            st4cs(oA,      oAl);
            st4cs(oA + 32, oAh);
        }

        if (hasB && ((rB == 0) || hasR1)) {
            float4 oBl = bilin4(wB, b00l, b01l, b10l, b11l);
            float4 oBh = bilin4(wB, b00h, b01h, b10h, b11h);
            float4* oB = out0 + ptB * C4V + lane;
            st4cs(oB,      oBl);
            st4cs(oB + 32, oBh);
        }
    }
}

extern "C" void kernel_launch(void* const* d_in, const int* in_sizes, int n_in,
                              void* d_out, int out_size)
{
    const float* boxes       = (const float*)d_in[0];
    const int*   image_shape = (const int*)d_in[1];
    const float* p2          = (const float*)d_in[2];
    const float* p3          = (const float*)d_in[3];
    const float* p4          = (const float*)d_in[4];
    const float* p5          = (const float*)d_in[5];
    float*       out         = (float*)d_out;

    int B = in_sizes[2] / (256 * 256 * 256);
    if (B < 1) B = 1;
    int N = in_sizes[0] / (4 * B);
    int nroi = B * N;
    int nblk = (nroi + 1) / 2;

    roi_align_kernel<<<nblk, 128>>>(boxes, image_shape, p2, p3, p4, p5, out,
                                    N, nroi);
}

// round 16
// speedup vs baseline: 1.5686x; 1.5686x over previous
#include <cuda_runtime.h>

// PyramidROIAlign, persistent blocks: 1000 blocks x 128 threads, each block
// handles 2 ROIs sequentially (roi = bid, bid + nblk) -> all blocks resident
// from t=0, no wave-2 tail. Inner body identical to the proven 33.3us kernel:
// per warp-iteration 2 points x 2 halves = 16 burst LDG.128, .cs stores.
// Output [B,N,7,7,256] f32.

#define POOLN   49
#define C4V     64
#define PER_ROI (POOLN * C4V)

#define LD4(v, addr)                                                           \
    asm volatile("ld.global.nc.v4.f32 {%0,%1,%2,%3}, [%4];"                    \
        : "=f"((v).x), "=f"((v).y), "=f"((v).z), "=f"((v).w) : "l"(addr))

__device__ __forceinline__ float4 bilin4(float4 wt, float4 a, float4 b,
                                         float4 c, float4 d)
{
    float4 o;
    o.x = wt.x * a.x + wt.y * b.x + wt.z * c.x + wt.w * d.x;
    o.y = wt.x * a.y + wt.y * b.y + wt.z * c.y + wt.w * d.y;
    o.z = wt.x * a.z + wt.y * b.z + wt.z * c.z + wt.w * d.z;
    o.w = wt.x * a.w + wt.y * b.w + wt.z * c.w + wt.w * d.w;
    return o;
}

__device__ __forceinline__ void st4cs(float4* addr, float4 v)
{
    asm volatile("st.global.cs.v4.f32 [%0], {%1,%2,%3,%4};"
        :: "l"(addr), "f"(v.x), "f"(v.y), "f"(v.z), "f"(v.w));
}

__global__ void __launch_bounds__(128, 4) roi_align_kernel(
    const float* __restrict__ boxes,       // [B,N,4]
    const int*   __restrict__ image_shape, // [2]
    const float* __restrict__ p2,
    const float* __restrict__ p3,
    const float* __restrict__ p4,
    const float* __restrict__ p5,
    float*       __restrict__ out,         // [B,N,7,7,256]
    int N, int nroi, int nblk)
{
    __shared__ int4   s_off[POOLN];
    __shared__ float4 s_w[POOLN];
    __shared__ int    s_lvl;

    const int tid  = threadIdx.x;
    const int lane = tid & 31;
    const int wid  = tid >> 5;             // 0..3

    for (int k = 0; k < 2; k++) {
        int roi = blockIdx.x + k * nblk;
        if (roi >= nroi) break;
        int b = roi / N;

        if (k > 0) __syncthreads();        // tables free before rebuild

        if (tid < POOLN) {
            const float* bx = boxes + roi * 4;
            float y1 = __ldg(bx + 0), x1 = __ldg(bx + 1);
            float y2 = __ldg(bx + 2), x2 = __ldg(bx + 3);
            float bh = y2 - y1, bw = x2 - x1;

            float img_area = (float)image_shape[0] * (float)image_shape[1];
            float scaled = sqrtf(bh * bw) * sqrtf(img_area) * (1.0f / 224.0f);
            float fl = rintf(log2f(scaled));
            fl = fminf(fmaxf(fl, -2.0f), 1.0f);     // lvl = 4+fl in [2,5]
            int lvl = 4 + (int)fl;
            int H = 256 >> (lvl - 2);
            int W = H;

            int py = tid / 7;
            int px = tid - py * 7;
            float ty = (float)py * (1.0f / 6.0f);
            float tx = (float)px * (1.0f / 6.0f);
            float ys = (y1 + bh * ty) * (float)(H - 1);
            float xs = (x1 + bw * tx) * (float)(W - 1);

            float y0f = floorf(ys);
            float x0f = floorf(xs);
            float wy = ys - y0f;
            float wx = xs - x0f;

            int y0  = min(H - 1, max(0, (int)y0f));
            int x0  = min(W - 1, max(0, (int)x0f));
            int y1i = min(H - 1, y0 + 1);
            int x1i = min(W - 1, x0 + 1);

            int base = b * H * W * C4V;         // float4 units, fits int32
            int r0 = base + y0  * W * C4V;
            int r1 = base + y1i * W * C4V;
            s_off[tid] = make_int4(r0 + x0  * C4V,
                                   r0 + x1i * C4V,
                                   r1 + x0  * C4V,
                                   r1 + x1i * C4V);

            float iwy = 1.0f - wy, iwx = 1.0f - wx;
            s_w[tid] = make_float4(iwy * iwx, iwy * wx, wy * iwx, wy * wx);

            if (tid == 0) s_lvl = lvl;
        }
        __syncthreads();

        const int lvl = s_lvl;
        const float4* __restrict__ fm4 =
            (lvl == 2) ? (const float4*)p2 :
            (lvl == 3) ? (const float4*)p3 :
            (lvl == 4) ? (const float4*)p4 : (const float4*)p5;

        float4* __restrict__ out4 = (float4*)out + (long long)roi * PER_ROI;

        for (int pt = wid; pt < POOLN; pt += 8) {
            int  ptB  = pt + 4;
            bool hasB = (ptB < POOLN);
            int  ptBs = hasB ? ptB : pt;

            int4   offA = s_off[pt],  offB = s_off[ptBs];
            float4 wA   = s_w[pt],    wB   = s_w[ptBs];

            const float4* pa0 = fm4 + offA.x + lane;
            const float4* pa1 = fm4 + offA.y + lane;
            const float4* pa2 = fm4 + offA.z + lane;
            const float4* pa3 = fm4 + offA.w + lane;
            const float4* pb0 = fm4 + offB.x + lane;
            const float4* pb1 = fm4 + offB.y + lane;
            const float4* pb2 = fm4 + offB.z + lane;
            const float4* pb3 = fm4 + offB.w + lane;

            float4 a00l, a01l, a10l, a11l, a00h, a01h, a10h, a11h;
            float4 b00l, b01l, b10l, b11l, b00h, b01h, b10h, b11h;

            // 16 back-to-back independent LDG.128
            LD4(a00l, pa0);      LD4(a01l, pa1);
            LD4(a10l, pa2);      LD4(a11l, pa3);
            LD4(a00h, pa0 + 32); LD4(a01h, pa1 + 32);
            LD4(a10h, pa2 + 32); LD4(a11h, pa3 + 32);
            LD4(b00l, pb0);      LD4(b01l, pb1);
            LD4(b10l, pb2);      LD4(b11l, pb3);
            LD4(b00h, pb0 + 32); LD4(b01h, pb1 + 32);
            LD4(b10h, pb2 + 32); LD4(b11h, pb3 + 32);

            float4 oAl = bilin4(wA, a00l, a01l, a10l, a11l);
            float4 oAh = bilin4(wA, a00h, a01h, a10h, a11h);

            float4* oA = out4 + pt * C4V + lane;
            st4cs(oA,      oAl);
            st4cs(oA + 32, oAh);

            if (hasB) {
                float4 oBl = bilin4(wB, b00l, b01l, b10l, b11l);
                float4 oBh = bilin4(wB, b00h, b01h, b10h, b11h);

                float4* oB = out4 + ptB * C4V + lane;
                st4cs(oB,      oBl);
                st4cs(oB + 32, oBh);
            }
        }
    }
}

extern "C" void kernel_launch(void* const* d_in, const int* in_sizes, int n_in,
                              void* d_out, int out_size)
{
    const float* boxes       = (const float*)d_in[0];
    const int*   image_shape = (const int*)d_in[1];
    const float* p2          = (const float*)d_in[2];
    const float* p3          = (const float*)d_in[3];
    const float* p4          = (const float*)d_in[4];
    const float* p5          = (const float*)d_in[5];
    float*       out         = (float*)d_out;

    int B = in_sizes[2] / (256 * 256 * 256);
    if (B < 1) B = 1;
    int N = in_sizes[0] / (4 * B);
    int nroi = B * N;
    int nblk = (nroi + 1) / 2;

    roi_align_kernel<<<nblk, 128>>>(boxes, image_shape, p2, p3, p4, p5, out,
                                    N, nroi, nblk);
}